// round 2
// baseline (speedup 1.0000x reference)
#include <cuda_runtime.h>

// Problem dims
#define HN 32
#define HC 64
#define HH 96
#define HWD 96
#define HWW 9216        // 96*96
#define K7 448          // C*7

// Scratch (device globals; no allocations allowed)
__device__ float g_t2[HN * HC * HC];     // (n, c, d) channel attention
__device__ float g_t6[HN * HWW];         // (n, h*w)
__device__ float g_t9[HN * HC];          // (n, c)
__device__ float g_t8[HN * K7 * HC];     // (n, k, c), includes 1/sqrt(448)

// ---- packed f32x2 helpers (sm_100+: doubles FP32 FMA rate; ptxas never emits these) ----
__device__ __forceinline__ unsigned long long ffma2(unsigned long long a,
                                                    unsigned long long b,
                                                    unsigned long long c) {
    unsigned long long d;
    asm("fma.rn.f32x2 %0, %1, %2, %3;" : "=l"(d) : "l"(a), "l"(b), "l"(c));
    return d;
}
__device__ __forceinline__ unsigned long long fpack2(float lo, float hi) {
    unsigned long long r;
    asm("mov.b64 %0, {%1, %2};" : "=l"(r) : "f"(lo), "f"(hi));
    return r;
}
__device__ __forceinline__ void funpack2(unsigned long long v, float& lo, float& hi) {
    asm("mov.b64 {%0, %1}, %2;" : "=f"(lo), "=f"(hi) : "l"(v));
}

// ---------------------------------------------------------------------------
// init: zero atomic accumulators (t2, t9)
// ---------------------------------------------------------------------------
__global__ void k_init() {
    int t = blockIdx.x * 256 + threadIdx.x;
    if (t < HN * HC * HC) g_t2[t] = 0.f;
    if (t < HN * HC)      g_t9[t] = 0.f;
}

// ---------------------------------------------------------------------------
// t2[n,c,d] = sum_s x[n,c,s] * x_roll[n,d,s] / 96
// split-K over s with atomics. Block = 64 threads, 64x64 tile, 8x8/thread,
// c-paired f32x2 accumulators. LDS demand tuned to exactly the 128B/cyc/SM cap.
// ---------------------------------------------------------------------------
#define T2_NCH 36
#define T2_CS  256   // 9216 / 36

__global__ void __launch_bounds__(64) k_t2(const float* __restrict__ x) {
    const int n = blockIdx.y;
    const int sbase0 = blockIdx.x * T2_CS;
    __shared__ __align__(16) float As[64][66];   // [s_local][c]  (t0)
    __shared__ __align__(16) float Bs[64][66];   // [s_local][d]  (t1 = rolled x)
    const int t = threadIdx.x;
    const int tx = t & 7, ty = t >> 3;
    const int c0 = ty * 8, d0 = tx * 8;

    unsigned long long acc[4][8];   // c pairs (4 x float2 = 8 c) x 8 d
#pragma unroll
    for (int u = 0; u < 4; u++)
#pragma unroll
        for (int v = 0; v < 8; v++) acc[u][v] = 0ULL;

    const float* xn = x + (size_t)n * HC * HWW;

    for (int st = 0; st < T2_CS; st += 64) {
        const int sbase = sbase0 + st;
        // load tiles: 64 threads x 64 iters
#pragma unroll 4
        for (int it = 0; it < 64; it++) {
            As[t][it] = xn[it * HWW + sbase + t];
            int s = sbase + t;
            int h = s / 96, w = s - h * 96;
            int src = ((h + 95) % 96) * 96 + (w + 1) % 96;
            Bs[t][it] = xn[it * HWW + src];
        }
        __syncthreads();
#pragma unroll 8
        for (int ks = 0; ks < 64; ks++) {
            unsigned long long a2[4];
#pragma unroll
            for (int u = 0; u < 4; u++)
                a2[u] = *(const unsigned long long*)&As[ks][c0 + 2 * u];
#pragma unroll
            for (int v = 0; v < 8; v++) {
                float b = Bs[ks][d0 + v];
                unsigned long long b2 = fpack2(b, b);
#pragma unroll
                for (int u = 0; u < 4; u++) acc[u][v] = ffma2(a2[u], b2, acc[u][v]);
            }
        }
        __syncthreads();
    }

    const float inv = 1.0f / 96.0f;
    float* t2p = g_t2 + n * HC * HC;
#pragma unroll
    for (int u = 0; u < 4; u++)
#pragma unroll
        for (int v = 0; v < 8; v++) {
            float lo, hi;
            funpack2(acc[u][v], lo, hi);
            atomicAdd(&t2p[(c0 + 2 * u) * HC + d0 + v], lo * inv);
            atomicAdd(&t2p[(c0 + 2 * u + 1) * HC + d0 + v], hi * inv);
        }
}

// ---------------------------------------------------------------------------
// t6[n,h,w] = sum_c p6[c] * dwconv3x3_dil2(t1)[n,c,h,w]
// t1 computed by index roll; conv zero-padding is on t1's domain.
// Block handles 16 rows x 96; loops channels with smem tile.
// ---------------------------------------------------------------------------
__global__ void __launch_bounds__(256) k_t6(const float* __restrict__ x,
                                            const float* __restrict__ w4,
                                            const float* __restrict__ p6) {
    const int n = blockIdx.y;
    const int h0 = blockIdx.x * 16;
    __shared__ float tile[20][104];   // t1 rows h0-2..h0+17, cols -2..97
    __shared__ float coef[9];
    const int t = threadIdx.x;
    float acc[6];
#pragma unroll
    for (int k = 0; k < 6; k++) acc[k] = 0.f;
    const float* xn = x + (size_t)n * HC * HWW;

    for (int c = 0; c < HC; c++) {
        if (t < 9) coef[t] = w4[c * 9 + t] * p6[c];
        for (int idx = t; idx < 20 * 104; idx += 256) {
            int r = idx / 104, cw = idx - r * 104;
            float v = 0.f;
            if (cw < 100) {
                int y = h0 - 2 + r;
                int xc = cw - 2;
                if (y >= 0 && y < 96 && xc >= 0 && xc < 96)
                    v = xn[c * HWW + ((y + 95) % 96) * 96 + (xc + 1) % 96];
            }
            tile[r][cw] = v;
        }
        __syncthreads();
#pragma unroll
        for (int k = 0; k < 6; k++) {
            int o = t + k * 256;
            int r = o / 96, w = o - r * 96;
            float s = 0.f;
#pragma unroll
            for (int u = 0; u < 3; u++)
#pragma unroll
                for (int v = 0; v < 3; v++)
                    s += coef[u * 3 + v] * tile[r + 2 * u][w + 2 * v];
            acc[k] += s;
        }
        __syncthreads();
    }
    float* t6n = g_t6 + n * HWW;
#pragma unroll
    for (int k = 0; k < 6; k++) {
        int o = t + k * 256;
        t6n[(h0 + o / 96) * 96 + (o % 96)] = acc[k];
    }
}

// ---------------------------------------------------------------------------
// t9[n,c] = (1/96) * sum_s dwconv5x5(t1)[n,c,s] * t6[n,s]
// grid (hchunk=4, c=64, n=32); block-reduce then one atomic per block.
// ---------------------------------------------------------------------------
#define T9_TH 24
__global__ void __launch_bounds__(256) k_t9(const float* __restrict__ x,
                                            const float* __restrict__ w3) {
    const int n = blockIdx.z;
    const int c = blockIdx.y;
    const int h0 = blockIdx.x * T9_TH;
    __shared__ float tile[28][104];   // t1 rows h0-2..h0+25, cols -2..97
    __shared__ float w3s[25];
    __shared__ float red[8];
    const int t = threadIdx.x;
    const float* xc = x + ((size_t)n * HC + c) * HWW;

    if (t < 25) w3s[t] = w3[c * 25 + t];
    for (int idx = t; idx < 28 * 104; idx += 256) {
        int r = idx / 104, cw = idx - r * 104;
        float v = 0.f;
        if (cw < 100) {
            int y = h0 - 2 + r;
            int xcc = cw - 2;
            if (y >= 0 && y < 96 && xcc >= 0 && xcc < 96)
                v = xc[((y + 95) % 96) * 96 + (xcc + 1) % 96];
        }
        tile[r][cw] = v;
    }
    __syncthreads();

    const float* t6n = g_t6 + n * HWW + h0 * 96;
    float local = 0.f;
#pragma unroll
    for (int k = 0; k < 9; k++) {        // 24*96 / 256 = 9
        int o = t + k * 256;
        int r = o / 96, w = o - r * 96;
        float s = 0.f;
#pragma unroll
        for (int u = 0; u < 5; u++)
#pragma unroll
            for (int v = 0; v < 5; v++)
                s += w3s[u * 5 + v] * tile[r + u][w + v];
        local += s * t6n[o];
    }
#pragma unroll
    for (int off = 16; off; off >>= 1) local += __shfl_down_sync(0xffffffffu, local, off);
    if ((t & 31) == 0) red[t >> 5] = local;
    __syncthreads();
    if (t < 8) {
        local = red[t];
#pragma unroll
        for (int off = 4; off; off >>= 1) local += __shfl_down_sync(0xffu, local, off);
        if (t == 0) atomicAdd(&g_t9[n * HC + c], local * (1.0f / 96.0f));
    }
}

// ---------------------------------------------------------------------------
// t8[n,d,c] = (1/sqrt(448)) * sum_b p5[b,c] * t2[n,b,c] * p8[b,d]
// ---------------------------------------------------------------------------
__global__ void __launch_bounds__(256) k_t8(const float* __restrict__ p5,
                                            const float* __restrict__ p8) {
    const int n = blockIdx.y;
    const int d0 = blockIdx.x * 32;
    __shared__ float t5s[64 * 64];
    __shared__ float p8s[64 * 32];
    const int t = threadIdx.x;
    const float* t2n = g_t2 + n * HC * HC;
    for (int idx = t; idx < 4096; idx += 256) t5s[idx] = p5[idx] * t2n[idx];
    for (int idx = t; idx < 2048; idx += 256) {
        int b = idx >> 5, dd = idx & 31;
        p8s[idx] = p8[b * K7 + d0 + dd];
    }
    __syncthreads();
    const float sc = 0.047245559126f;   // 1/sqrt(448)
#pragma unroll
    for (int k = 0; k < 8; k++) {
        int o = t + k * 256;
        int dl = o >> 6, c = o & 63;
        float s = 0.f;
#pragma unroll 8
        for (int b = 0; b < 64; b++) s += t5s[b * 64 + c] * p8s[b * 32 + dl];
        g_t8[((size_t)n * K7 + d0 + dl) * HC + c] = s * sc;
    }
}

// ---------------------------------------------------------------------------
// out[n,c,s] = t9[n,c] + sum_{c',j} t8[n,c'*7+j,c] * x[n,c',h,w+2j-6]
// Implicit GEMM over the unfold: M=64 (c), N=9216 (s), K=448. Block = 2 rows
// x 96 w x all 64 c; 128 threads; thread tile = 16c x 6s with c-paired f32x2.
// ---------------------------------------------------------------------------
__global__ void __launch_bounds__(128) k_out(const float* __restrict__ x,
                                             float* __restrict__ out) {
    const int n = blockIdx.y;
    const int h0 = blockIdx.x * 2;
    __shared__ __align__(16) float xs[2][108];    // w' in [-6, 101] for 2 rows
    __shared__ __align__(16) float t8s[7][64];    // [j][c] slice for channel c'
    const int t = threadIdx.x;
    const int tx = t & 31, ty = t >> 5;
    const int c0 = ty * 16;
    const int row = tx >> 4;              // 0/1
    const int w0 = (tx & 15) * 6;

    unsigned long long acc[8][6];         // 8 c-pairs x 6 s
#pragma unroll
    for (int i = 0; i < 8; i++)
#pragma unroll
        for (int q = 0; q < 6; q++) acc[i][q] = 0ULL;

    const float* xn = x + (size_t)n * HC * HWW;
    const float* t8n = g_t8 + (size_t)n * K7 * HC;

    for (int cp = 0; cp < HC; cp++) {
        __syncthreads();
        for (int idx = t; idx < 216; idx += 128) {
            int r = idx / 108, cw = idx - r * 108;
            int wq = cw - 6;
            xs[r][cw] = (wq >= 0 && wq < 96) ? xn[cp * HWW + (h0 + r) * 96 + wq] : 0.f;
        }
        for (int idx = t; idx < 448; idx += 128)
            ((float*)t8s)[idx] = t8n[cp * 448 + idx];
        __syncthreads();
#pragma unroll
        for (int j = 0; j < 7; j++) {
            unsigned long long xp[6];
#pragma unroll
            for (int q = 0; q < 6; q++) {
                float v = xs[row][w0 + q + 2 * j];
                xp[q] = fpack2(v, v);
            }
#pragma unroll
            for (int i = 0; i < 8; i++) {
                unsigned long long a2 =
                    *(const unsigned long long*)&t8s[j][c0 + 2 * i];
#pragma unroll
                for (int q = 0; q < 6; q++) acc[i][q] = ffma2(a2, xp[q], acc[i][q]);
            }
        }
    }

    // epilogue: add t9 broadcast, write
    float t9v[16];
#pragma unroll
    for (int i = 0; i < 16; i++) t9v[i] = g_t9[n * HC + c0 + i];
    const int srow = (h0 + row) * 96 + w0;
#pragma unroll
    for (int i = 0; i < 8; i++)
#pragma unroll
        for (int q = 0; q < 6; q++) {
            float lo, hi;
            funpack2(acc[i][q], lo, hi);
            int s = srow + q;
            out[((size_t)(n * HC + c0 + 2 * i)) * HWW + s] = lo + t9v[2 * i];
            out[((size_t)(n * HC + c0 + 2 * i + 1)) * HWW + s] = hi + t9v[2 * i + 1];
        }
}

// ---------------------------------------------------------------------------
extern "C" void kernel_launch(void* const* d_in, const int* in_sizes, int n_in,
                              void* d_out, int out_size) {
    const float* x  = (const float*)d_in[0];
    const float* w3 = (const float*)d_in[1];
    const float* w4 = (const float*)d_in[2];
    const float* p5 = (const float*)d_in[3];
    const float* p6 = (const float*)d_in[4];
    const float* p8 = (const float*)d_in[5];
    float* out = (float*)d_out;

    k_init<<<512, 256>>>();
    k_t2<<<dim3(T2_NCH, HN), 64>>>(x);
    k_t6<<<dim3(6, HN), 256>>>(x, w4, p6);
    k_t9<<<dim3(4, HC, HN), 256>>>(x, w3);
    k_t8<<<dim3(14, HN), 256>>>(p5, p8);
    k_out<<<dim3(48, HN), 128>>>(x, out);
}

// round 3
// speedup vs baseline: 1.5748x; 1.5748x over previous
#include <cuda_runtime.h>

// Problem dims
#define HN 32
#define HC 64
#define HH 96
#define HWD 96
#define HWW 9216        // 96*96
#define K7 448          // C*7

// Scratch (device globals; no allocations allowed)
__device__ float g_t2[HN * HC * HC];     // (n, c, d) channel attention
__device__ float g_t6[HN * HWW];         // (n, h*w)
__device__ float g_t9[HN * HC];          // (n, c)
__device__ float g_t8[HN * K7 * HC];     // (n, k, c), includes 1/sqrt(448)

// ---- packed f32x2 helpers ----
__device__ __forceinline__ unsigned long long ffma2(unsigned long long a,
                                                    unsigned long long b,
                                                    unsigned long long c) {
    unsigned long long d;
    asm("fma.rn.f32x2 %0, %1, %2, %3;" : "=l"(d) : "l"(a), "l"(b), "l"(c));
    return d;
}
__device__ __forceinline__ unsigned long long fpack2(float lo, float hi) {
    unsigned long long r;
    asm("mov.b64 %0, {%1, %2};" : "=l"(r) : "f"(lo), "f"(hi));
    return r;
}
__device__ __forceinline__ void funpack2(unsigned long long v, float& lo, float& hi) {
    asm("mov.b64 {%0, %1}, %2;" : "=f"(lo), "=f"(hi) : "l"(v));
}

// ---------------------------------------------------------------------------
// init: zero atomic accumulators (t2, t9)
// ---------------------------------------------------------------------------
__global__ void k_init() {
    int t = blockIdx.x * 256 + threadIdx.x;
    if (t < HN * HC * HC) g_t2[t] = 0.f;
    if (t < HN * HC)      g_t9[t] = 0.f;
}

// ---------------------------------------------------------------------------
// t2[n,c,d] = sum_s x[n,c,s] * x_roll[n,d,s] / 96   (unchanged from R1)
// ---------------------------------------------------------------------------
#define T2_NCH 36
#define T2_CS  256   // 9216 / 36

__global__ void __launch_bounds__(64) k_t2(const float* __restrict__ x) {
    const int n = blockIdx.y;
    const int sbase0 = blockIdx.x * T2_CS;
    __shared__ __align__(16) float As[64][66];   // [s_local][c]  (t0)
    __shared__ __align__(16) float Bs[64][66];   // [s_local][d]  (t1 = rolled x)
    const int t = threadIdx.x;
    const int tx = t & 7, ty = t >> 3;
    const int c0 = ty * 8, d0 = tx * 8;

    unsigned long long acc[4][8];
#pragma unroll
    for (int u = 0; u < 4; u++)
#pragma unroll
        for (int v = 0; v < 8; v++) acc[u][v] = 0ULL;

    const float* xn = x + (size_t)n * HC * HWW;

    for (int st = 0; st < T2_CS; st += 64) {
        const int sbase = sbase0 + st;
#pragma unroll 4
        for (int it = 0; it < 64; it++) {
            As[t][it] = xn[it * HWW + sbase + t];
            int s = sbase + t;
            int h = s / 96, w = s - h * 96;
            int src = ((h + 95) % 96) * 96 + (w + 1) % 96;
            Bs[t][it] = xn[it * HWW + src];
        }
        __syncthreads();
#pragma unroll 8
        for (int ks = 0; ks < 64; ks++) {
            unsigned long long a2[4];
#pragma unroll
            for (int u = 0; u < 4; u++)
                a2[u] = *(const unsigned long long*)&As[ks][c0 + 2 * u];
#pragma unroll
            for (int v = 0; v < 8; v++) {
                float b = Bs[ks][d0 + v];
                unsigned long long b2 = fpack2(b, b);
#pragma unroll
                for (int u = 0; u < 4; u++) acc[u][v] = ffma2(a2[u], b2, acc[u][v]);
            }
        }
        __syncthreads();
    }

    const float inv = 1.0f / 96.0f;
    float* t2p = g_t2 + n * HC * HC;
#pragma unroll
    for (int u = 0; u < 4; u++)
#pragma unroll
        for (int v = 0; v < 8; v++) {
            float lo, hi;
            funpack2(acc[u][v], lo, hi);
            atomicAdd(&t2p[(c0 + 2 * u) * HC + d0 + v], lo * inv);
            atomicAdd(&t2p[(c0 + 2 * u + 1) * HC + d0 + v], hi * inv);
        }
}

// ---------------------------------------------------------------------------
// t6[n,h,w] = sum_c p6[c] * dwconv3x3_dil2(t1)[n,c,h,w]
// grid (12, n): 8 rows per block for better SM fill (384 blocks).
// ---------------------------------------------------------------------------
__global__ void __launch_bounds__(256) k_t6(const float* __restrict__ x,
                                            const float* __restrict__ w4,
                                            const float* __restrict__ p6) {
    const int n = blockIdx.y;
    const int h0 = blockIdx.x * 8;
    __shared__ float tile[12][104];   // t1 rows h0-2..h0+9, cols -2..97
    __shared__ float coef[9];
    const int t = threadIdx.x;
    float acc[3];
#pragma unroll
    for (int k = 0; k < 3; k++) acc[k] = 0.f;
    const float* xn = x + (size_t)n * HC * HWW;

    for (int c = 0; c < HC; c++) {
        if (t < 9) coef[t] = w4[c * 9 + t] * p6[c];
        for (int idx = t; idx < 12 * 104; idx += 256) {
            int r = idx / 104, cw = idx - r * 104;
            float v = 0.f;
            if (cw < 100) {
                int y = h0 - 2 + r;
                int xc = cw - 2;
                if (y >= 0 && y < 96 && xc >= 0 && xc < 96)
                    v = xn[c * HWW + ((y + 95) % 96) * 96 + (xc + 1) % 96];
            }
            tile[r][cw] = v;
        }
        __syncthreads();
#pragma unroll
        for (int k = 0; k < 3; k++) {
            int o = t + k * 256;
            int r = o / 96, w = o - r * 96;
            float s = 0.f;
#pragma unroll
            for (int u = 0; u < 3; u++)
#pragma unroll
                for (int v = 0; v < 3; v++)
                    s += coef[u * 3 + v] * tile[r + 2 * u][w + 2 * v];
            acc[k] += s;
        }
        __syncthreads();
    }
    float* t6n = g_t6 + n * HWW;
#pragma unroll
    for (int k = 0; k < 3; k++) {
        int o = t + k * 256;
        t6n[(h0 + o / 96) * 96 + (o % 96)] = acc[k];
    }
}

// ---------------------------------------------------------------------------
// t9[n,c] = (1/96) * sum_s dwconv5x5(t1)[n,c,s] * t6[n,s]
// Register-blocked: each thread computes a vertical quad of conv outputs
// (40 LDS per 100 FMA instead of 100). grid (3, c, n), 32 rows per block.
// ---------------------------------------------------------------------------
__global__ void __launch_bounds__(256) k_t9(const float* __restrict__ x,
                                            const float* __restrict__ w3) {
    const int n = blockIdx.z;
    const int c = blockIdx.y;
    const int h0 = blockIdx.x * 32;
    __shared__ float tile[36][104];   // t1 rows h0-2..h0+33, cols -2..97
    __shared__ float w3s[25];
    __shared__ float red[8];
    const int t = threadIdx.x;
    const float* xc = x + ((size_t)n * HC + c) * HWW;

    if (t < 25) w3s[t] = w3[c * 25 + t];
    for (int idx = t; idx < 36 * 104; idx += 256) {
        int r = idx / 104, cw = idx - r * 104;
        float v = 0.f;
        if (cw < 100) {
            int y = h0 - 2 + r;
            int xcc = cw - 2;
            if (y >= 0 && y < 96 && xcc >= 0 && xcc < 96)
                v = xc[((y + 95) % 96) * 96 + (xcc + 1) % 96];
        }
        tile[r][cw] = v;
    }
    __syncthreads();

    const float* t6n = g_t6 + n * HWW;
    float local = 0.f;
#pragma unroll
    for (int pass = 0; pass < 3; pass++) {     // 32*96/4 = 768 quads, 256 thr
        int q = t + pass * 256;
        int w = q % 96;
        int r0 = (q / 96) * 4;                 // output rows h0+r0 .. +3
        float a0 = 0.f, a1 = 0.f, a2 = 0.f, a3 = 0.f;
#pragma unroll
        for (int u = 0; u < 8; u++) {          // tile rows r0+u (= out row r0+k, tap u-k)
            float v0 = tile[r0 + u][w + 0];
            float v1 = tile[r0 + u][w + 1];
            float v2 = tile[r0 + u][w + 2];
            float v3 = tile[r0 + u][w + 3];
            float v4 = tile[r0 + u][w + 4];
            if (u <= 4 && u >= 0) {  // k=0 uses u 0..4
                const float* wr = &w3s[u * 5];
                a0 += wr[0]*v0 + wr[1]*v1 + wr[2]*v2 + wr[3]*v3 + wr[4]*v4;
            }
            if (u >= 1 && u <= 5) {  // k=1 uses tap u-1
                const float* wr = &w3s[(u - 1) * 5];
                a1 += wr[0]*v0 + wr[1]*v1 + wr[2]*v2 + wr[3]*v3 + wr[4]*v4;
            }
            if (u >= 2 && u <= 6) {
                const float* wr = &w3s[(u - 2) * 5];
                a2 += wr[0]*v0 + wr[1]*v1 + wr[2]*v2 + wr[3]*v3 + wr[4]*v4;
            }
            if (u >= 3) {            // k=3 uses tap u-3, u up to 7
                const float* wr = &w3s[(u - 3) * 5];
                a3 += wr[0]*v0 + wr[1]*v1 + wr[2]*v2 + wr[3]*v3 + wr[4]*v4;
            }
        }
        const float* t6q = t6n + (h0 + r0) * 96 + w;
        local += a0 * t6q[0] + a1 * t6q[96] + a2 * t6q[192] + a3 * t6q[288];
    }
#pragma unroll
    for (int off = 16; off; off >>= 1) local += __shfl_down_sync(0xffffffffu, local, off);
    if ((t & 31) == 0) red[t >> 5] = local;
    __syncthreads();
    if (t < 8) {
        local = red[t];
#pragma unroll
        for (int off = 4; off; off >>= 1) local += __shfl_down_sync(0xffu, local, off);
        if (t == 0) atomicAdd(&g_t9[n * HC + c], local * (1.0f / 96.0f));
    }
}

// ---------------------------------------------------------------------------
// t8[n,d,c] = (1/sqrt(448)) * sum_b p5[b,c] * t2[n,b,c] * p8[b,d]  (unchanged)
// ---------------------------------------------------------------------------
__global__ void __launch_bounds__(256) k_t8(const float* __restrict__ p5,
                                            const float* __restrict__ p8) {
    const int n = blockIdx.y;
    const int d0 = blockIdx.x * 32;
    __shared__ float t5s[64 * 64];
    __shared__ float p8s[64 * 32];
    const int t = threadIdx.x;
    const float* t2n = g_t2 + n * HC * HC;
    for (int idx = t; idx < 4096; idx += 256) t5s[idx] = p5[idx] * t2n[idx];
    for (int idx = t; idx < 2048; idx += 256) {
        int b = idx >> 5, dd = idx & 31;
        p8s[idx] = p8[b * K7 + d0 + dd];
    }
    __syncthreads();
    const float sc = 0.047245559126f;   // 1/sqrt(448)
#pragma unroll
    for (int k = 0; k < 8; k++) {
        int o = t + k * 256;
        int dl = o >> 6, c = o & 63;
        float s = 0.f;
#pragma unroll 8
        for (int b = 0; b < 64; b++) s += t5s[b * 64 + c] * p8s[b * 32 + dl];
        g_t8[((size_t)n * K7 + d0 + dl) * HC + c] = s * sc;
    }
}

// ---------------------------------------------------------------------------
// out[n,c,s] = t9[n,c] + sum_{c',j} t8[n,c'*7+j,c] * x[n,c',h,w+2j-6]
// Implicit GEMM over the unfold. 128 threads, 2 rows x 96 s x 64 c per block.
// Thread tile 16c x 6s (interleaved s: s = (tx&15) + 16q -> coalesced STG).
// Double-buffered smem so LDG latency overlaps the FFMA stream.
// ---------------------------------------------------------------------------
__global__ void __launch_bounds__(128) k_out(const float* __restrict__ x,
                                             float* __restrict__ out) {
    const int n = blockIdx.y;
    const int h0 = blockIdx.x * 2;
    __shared__ __align__(16) float xs[2][2][112];   // [buf][row][w'+6], w' in [-6,101]
    __shared__ __align__(16) float t8s[2][7][64];   // [buf][j][c]
    const int t = threadIdx.x;
    const int tx = t & 31, ty = t >> 5;
    const int c0 = ty * 16;
    const int row = tx >> 4;              // 0/1
    const int sw = tx & 15;               // interleaved s-lane

    unsigned long long acc[8][6];         // 8 c-pairs x 6 s (s = sw + 16q)
#pragma unroll
    for (int i = 0; i < 8; i++)
#pragma unroll
        for (int q = 0; q < 6; q++) acc[i][q] = 0ULL;

    const float* xn = x + (size_t)n * HC * HWW;
    const float* t8n = g_t8 + (size_t)n * K7 * HC;

    // prologue: load cp=0 into buffer 0
    {
        for (int idx = t; idx < 216; idx += 128) {
            int r = idx / 108, cw = idx - r * 108;
            int wq = cw - 6;
            xs[0][r][cw] = (wq >= 0 && wq < 96) ? xn[(h0 + r) * 96 + wq] : 0.f;
        }
        for (int idx = t; idx < 448; idx += 128)
            ((float*)t8s[0])[idx] = t8n[idx];
    }
    __syncthreads();

    for (int cp = 0; cp < HC; cp++) {
        const int cur = cp & 1;
        const int nxt = cur ^ 1;
        if (cp + 1 < HC) {
            const float* xrow = xn + (cp + 1) * HWW;
            const float* t8row = t8n + (cp + 1) * 448;
            for (int idx = t; idx < 216; idx += 128) {
                int r = idx / 108, cw = idx - r * 108;
                int wq = cw - 6;
                xs[nxt][r][cw] = (wq >= 0 && wq < 96) ? xrow[(h0 + r) * 96 + wq] : 0.f;
            }
            for (int idx = t; idx < 448; idx += 128)
                ((float*)t8s[nxt])[idx] = t8row[idx];
        }
#pragma unroll
        for (int j = 0; j < 7; j++) {
            unsigned long long xp[6];
#pragma unroll
            for (int q = 0; q < 6; q++) {
                float v = xs[cur][row][sw + 16 * q + 2 * j];
                xp[q] = fpack2(v, v);
            }
#pragma unroll
            for (int i = 0; i < 8; i++) {
                unsigned long long a2 =
                    *(const unsigned long long*)&t8s[cur][j][c0 + 2 * i];
#pragma unroll
                for (int q = 0; q < 6; q++) acc[i][q] = ffma2(a2, xp[q], acc[i][q]);
            }
        }
        __syncthreads();
    }

    // epilogue: add t9 broadcast, coalesced stores
    float t9v[16];
#pragma unroll
    for (int i = 0; i < 16; i++) t9v[i] = g_t9[n * HC + c0 + i];
    const int srow = (h0 + row) * 96 + sw;
#pragma unroll
    for (int i = 0; i < 8; i++)
#pragma unroll
        for (int q = 0; q < 6; q++) {
            float lo, hi;
            funpack2(acc[i][q], lo, hi);
            int s = srow + 16 * q;
            out[((size_t)(n * HC + c0 + 2 * i)) * HWW + s] = lo + t9v[2 * i];
            out[((size_t)(n * HC + c0 + 2 * i + 1)) * HWW + s] = hi + t9v[2 * i + 1];
        }
}

// ---------------------------------------------------------------------------
extern "C" void kernel_launch(void* const* d_in, const int* in_sizes, int n_in,
                              void* d_out, int out_size) {
    const float* x  = (const float*)d_in[0];
    const float* w3 = (const float*)d_in[1];
    const float* w4 = (const float*)d_in[2];
    const float* p5 = (const float*)d_in[3];
    const float* p6 = (const float*)d_in[4];
    const float* p8 = (const float*)d_in[5];
    float* out = (float*)d_out;

    k_init<<<512, 256>>>();
    k_t2<<<dim3(T2_NCH, HN), 64>>>(x);
    k_t6<<<dim3(12, HN), 256>>>(x, w4, p6);
    k_t9<<<dim3(3, HC, HN), 256>>>(x, w3);
    k_t8<<<dim3(14, HN), 256>>>(p5, p8);
    k_out<<<dim3(48, HN), 128>>>(x, out);
}

// round 6
// speedup vs baseline: 2.2881x; 1.4530x over previous
#include <cuda_runtime.h>
#include <cuda_bf16.h>
#include <cstdint>

// Problem dims
#define HN 32
#define HC 64
#define HH 96
#define HWD 96
#define HWW 9216        // 96*96
#define K7 448          // C*7

// Scratch (device globals; no allocations allowed)
__device__ float g_t2[HN * HC * HC];     // (n, c, d) channel attention
__device__ float g_t6[HN * HWW];         // (n, h*w)
__device__ float g_t9[HN * HC];          // (n, c)
__device__ float g_t8[HN * HC * K7];     // (n, c, k) TRANSPOSED, incl 1/sqrt(448)

// ---- packed f32x2 helpers (used by k_t2) ----
__device__ __forceinline__ unsigned long long ffma2(unsigned long long a,
                                                    unsigned long long b,
                                                    unsigned long long c) {
    unsigned long long d;
    asm("fma.rn.f32x2 %0, %1, %2, %3;" : "=l"(d) : "l"(a), "l"(b), "l"(c));
    return d;
}
__device__ __forceinline__ unsigned long long fpack2(float lo, float hi) {
    unsigned long long r;
    asm("mov.b64 %0, {%1, %2};" : "=l"(r) : "f"(lo), "f"(hi));
    return r;
}
__device__ __forceinline__ void funpack2(unsigned long long v, float& lo, float& hi) {
    asm("mov.b64 {%0, %1}, %2;" : "=f"(lo), "=f"(hi) : "l"(v));
}

// ---- bf16 helpers ----
__device__ __forceinline__ uint32_t bfpair(float e0, float e1) {
    // packs {low16 = bf16(e0), high16 = bf16(e1)}
    uint32_t r;
    asm("cvt.rn.bf16x2.f32 %0, %1, %2;" : "=r"(r) : "f"(e1), "f"(e0));
    return r;
}
__device__ __forceinline__ float bfround(float v) {
    return __bfloat162float(__float2bfloat16_rn(v));
}

// ---- warp mma: D(16x8,f32) += A(16x16,bf16) * B(16x8,bf16) ----
__device__ __forceinline__ void mma16816(float* d, const uint32_t* a,
                                         uint32_t b0, uint32_t b1) {
    asm volatile(
        "mma.sync.aligned.m16n8k16.row.col.f32.bf16.bf16.f32 "
        "{%0,%1,%2,%3}, {%4,%5,%6,%7}, {%8,%9}, {%0,%1,%2,%3};"
        : "+f"(d[0]), "+f"(d[1]), "+f"(d[2]), "+f"(d[3])
        : "r"(a[0]), "r"(a[1]), "r"(a[2]), "r"(a[3]), "r"(b0), "r"(b1));
}

// ---------------------------------------------------------------------------
__global__ void k_init() {
    int t = blockIdx.x * 256 + threadIdx.x;
    if (t < HN * HC * HC) g_t2[t] = 0.f;
    if (t < HN * HC)      g_t9[t] = 0.f;
}

// ---------------------------------------------------------------------------
// t2[n,c,d] = sum_s x[n,c,s] * x_roll[n,d,s] / 96   (unchanged)
// ---------------------------------------------------------------------------
#define T2_NCH 36
#define T2_CS  256

__global__ void __launch_bounds__(64) k_t2(const float* __restrict__ x) {
    const int n = blockIdx.y;
    const int sbase0 = blockIdx.x * T2_CS;
    __shared__ __align__(16) float As[64][66];
    __shared__ __align__(16) float Bs[64][66];
    const int t = threadIdx.x;
    const int tx = t & 7, ty = t >> 3;
    const int c0 = ty * 8, d0 = tx * 8;

    unsigned long long acc[4][8];
#pragma unroll
    for (int u = 0; u < 4; u++)
#pragma unroll
        for (int v = 0; v < 8; v++) acc[u][v] = 0ULL;

    const float* xn = x + (size_t)n * HC * HWW;

    for (int st = 0; st < T2_CS; st += 64) {
        const int sbase = sbase0 + st;
#pragma unroll 4
        for (int it = 0; it < 64; it++) {
            As[t][it] = xn[it * HWW + sbase + t];
            int s = sbase + t;
            int h = s / 96, w = s - h * 96;
            int src = ((h + 95) % 96) * 96 + (w + 1) % 96;
            Bs[t][it] = xn[it * HWW + src];
        }
        __syncthreads();
#pragma unroll 8
        for (int ks = 0; ks < 64; ks++) {
            unsigned long long a2[4];
#pragma unroll
            for (int u = 0; u < 4; u++)
                a2[u] = *(const unsigned long long*)&As[ks][c0 + 2 * u];
#pragma unroll
            for (int v = 0; v < 8; v++) {
                float b = Bs[ks][d0 + v];
                unsigned long long b2 = fpack2(b, b);
#pragma unroll
                for (int u = 0; u < 4; u++) acc[u][v] = ffma2(a2[u], b2, acc[u][v]);
            }
        }
        __syncthreads();
    }

    const float inv = 1.0f / 96.0f;
    float* t2p = g_t2 + n * HC * HC;
#pragma unroll
    for (int u = 0; u < 4; u++)
#pragma unroll
        for (int v = 0; v < 8; v++) {
            float lo, hi;
            funpack2(acc[u][v], lo, hi);
            atomicAdd(&t2p[(c0 + 2 * u) * HC + d0 + v], lo * inv);
            atomicAdd(&t2p[(c0 + 2 * u + 1) * HC + d0 + v], hi * inv);
        }
}

// ---------------------------------------------------------------------------
// t6 (unchanged)
// ---------------------------------------------------------------------------
__global__ void __launch_bounds__(256) k_t6(const float* __restrict__ x,
                                            const float* __restrict__ w4,
                                            const float* __restrict__ p6) {
    const int n = blockIdx.y;
    const int h0 = blockIdx.x * 8;
    __shared__ float tile[12][104];
    __shared__ float coef[9];
    const int t = threadIdx.x;
    float acc[3];
#pragma unroll
    for (int k = 0; k < 3; k++) acc[k] = 0.f;
    const float* xn = x + (size_t)n * HC * HWW;

    for (int c = 0; c < HC; c++) {
        if (t < 9) coef[t] = w4[c * 9 + t] * p6[c];
        for (int idx = t; idx < 12 * 104; idx += 256) {
            int r = idx / 104, cw = idx - r * 104;
            float v = 0.f;
            if (cw < 100) {
                int y = h0 - 2 + r;
                int xc = cw - 2;
                if (y >= 0 && y < 96 && xc >= 0 && xc < 96)
                    v = xn[c * HWW + ((y + 95) % 96) * 96 + (xc + 1) % 96];
            }
            tile[r][cw] = v;
        }
        __syncthreads();
#pragma unroll
        for (int k = 0; k < 3; k++) {
            int o = t + k * 256;
            int r = o / 96, w = o - r * 96;
            float s = 0.f;
#pragma unroll
            for (int u = 0; u < 3; u++)
#pragma unroll
                for (int v = 0; v < 3; v++)
                    s += coef[u * 3 + v] * tile[r + 2 * u][w + 2 * v];
            acc[k] += s;
        }
        __syncthreads();
    }
    float* t6n = g_t6 + n * HWW;
#pragma unroll
    for (int k = 0; k < 3; k++) {
        int o = t + k * 256;
        t6n[(h0 + o / 96) * 96 + (o % 96)] = acc[k];
    }
}

// ---------------------------------------------------------------------------
// t9 (unchanged)
// ---------------------------------------------------------------------------
__global__ void __launch_bounds__(256) k_t9(const float* __restrict__ x,
                                            const float* __restrict__ w3) {
    const int n = blockIdx.z;
    const int c = blockIdx.y;
    const int h0 = blockIdx.x * 32;
    __shared__ float tile[36][104];
    __shared__ float w3s[25];
    __shared__ float red[8];
    const int t = threadIdx.x;
    const float* xc = x + ((size_t)n * HC + c) * HWW;

    if (t < 25) w3s[t] = w3[c * 25 + t];
    for (int idx = t; idx < 36 * 104; idx += 256) {
        int r = idx / 104, cw = idx - r * 104;
        float v = 0.f;
        if (cw < 100) {
            int y = h0 - 2 + r;
            int xcc = cw - 2;
            if (y >= 0 && y < 96 && xcc >= 0 && xcc < 96)
                v = xc[((y + 95) % 96) * 96 + (xcc + 1) % 96];
        }
        tile[r][cw] = v;
    }
    __syncthreads();

    const float* t6n = g_t6 + n * HWW;
    float local = 0.f;
#pragma unroll
    for (int pass = 0; pass < 3; pass++) {
        int q = t + pass * 256;
        int w = q % 96;
        int r0 = (q / 96) * 4;
        float a0 = 0.f, a1 = 0.f, a2 = 0.f, a3 = 0.f;
#pragma unroll
        for (int u = 0; u < 8; u++) {
            float v0 = tile[r0 + u][w + 0];
            float v1 = tile[r0 + u][w + 1];
            float v2 = tile[r0 + u][w + 2];
            float v3 = tile[r0 + u][w + 3];
            float v4 = tile[r0 + u][w + 4];
            if (u <= 4) {
                const float* wr = &w3s[u * 5];
                a0 += wr[0]*v0 + wr[1]*v1 + wr[2]*v2 + wr[3]*v3 + wr[4]*v4;
            }
            if (u >= 1 && u <= 5) {
                const float* wr = &w3s[(u - 1) * 5];
                a1 += wr[0]*v0 + wr[1]*v1 + wr[2]*v2 + wr[3]*v3 + wr[4]*v4;
            }
            if (u >= 2 && u <= 6) {
                const float* wr = &w3s[(u - 2) * 5];
                a2 += wr[0]*v0 + wr[1]*v1 + wr[2]*v2 + wr[3]*v3 + wr[4]*v4;
            }
            if (u >= 3) {
                const float* wr = &w3s[(u - 3) * 5];
                a3 += wr[0]*v0 + wr[1]*v1 + wr[2]*v2 + wr[3]*v3 + wr[4]*v4;
            }
        }
        const float* t6q = t6n + (h0 + r0) * 96 + w;
        local += a0 * t6q[0] + a1 * t6q[96] + a2 * t6q[192] + a3 * t6q[288];
    }
#pragma unroll
    for (int off = 16; off; off >>= 1) local += __shfl_down_sync(0xffffffffu, local, off);
    if ((t & 31) == 0) red[t >> 5] = local;
    __syncthreads();
    if (t < 8) {
        local = red[t];
#pragma unroll
        for (int off = 4; off; off >>= 1) local += __shfl_down_sync(0xffu, local, off);
        if (t == 0) atomicAdd(&g_t9[n * HC + c], local * (1.0f / 96.0f));
    }
}

// ---------------------------------------------------------------------------
// t8: writes TRANSPOSED layout g_t8[n][c][k] (k contiguous).
// ---------------------------------------------------------------------------
__global__ void __launch_bounds__(256) k_t8(const float* __restrict__ p5,
                                            const float* __restrict__ p8) {
    const int n = blockIdx.y;
    const int d0 = blockIdx.x * 32;
    __shared__ float t5s[64 * 64];
    __shared__ float p8s[64 * 32];
    const int t = threadIdx.x;
    const float* t2n = g_t2 + n * HC * HC;
    for (int idx = t; idx < 4096; idx += 256) t5s[idx] = p5[idx] * t2n[idx];
    for (int idx = t; idx < 2048; idx += 256) {
        int b = idx >> 5, dd = idx & 31;
        p8s[idx] = p8[b * K7 + d0 + dd];
    }
    __syncthreads();
    const float sc = 0.047245559126f;   // 1/sqrt(448)
#pragma unroll
    for (int k = 0; k < 8; k++) {
        int o = t + k * 256;
        int dl = o >> 6, c = o & 63;
        float s = 0.f;
#pragma unroll 8
        for (int b = 0; b < 64; b++) s += t5s[b * 64 + c] * p8s[b * 32 + dl];
        g_t8[((size_t)(n * HC + c)) * K7 + d0 + dl] = s * sc;
    }
}

// ---------------------------------------------------------------------------
// k_out: warp-level mma.sync bf16 implicit GEMM (3-product compensated).
// Per block: D[c=64, s=128] = sum_k t8T[c,k] * u[k,s], K=448 = 28 steps of 16.
// 8 warps: warp_m = wid&3 (16 c-rows), warp_n = wid>>2 (64 s-cols, 8 n-tiles).
// A/B tiles in smem as bf16x2 words, row stride 9 words (conflict padding).
// ---------------------------------------------------------------------------
__global__ void __launch_bounds__(256) k_out_mma(const float* __restrict__ x,
                                                 float* __restrict__ out) {
    const int n = blockIdx.y;
    const int s0 = blockIdx.x * 128;
    __shared__ uint32_t A_hi[64 * 9], A_lo[64 * 9];
    __shared__ uint32_t B_hi[128 * 9], B_lo[128 * 9];
    __shared__ float t9s[64];
    const int t = threadIdx.x;
    const int wid = t >> 5, lane = t & 31;
    const int warp_m = wid & 3, warp_n = wid >> 2;
    const int lr = lane >> 2;     // 0..7
    const int lp = lane & 3;      // pair index 0..3

    if (t < 64) t9s[t] = g_t9[n * HC + t];

    float d[8][4];
#pragma unroll
    for (int i = 0; i < 8; i++)
#pragma unroll
        for (int q = 0; q < 4; q++) d[i][q] = 0.f;

    const float* xn = x + (size_t)n * HC * HWW;
    const float* t8n = g_t8 + (size_t)n * HC * K7;

    for (int ks = 0; ks < 28; ks++) {
        const int k0 = ks * 16;
        __syncthreads();   // previous iter's fragment LDS done before overwrite
        // ---- A build: 64 c x 16 k -> 512 bf16x2 words (hi & lo) ----
#pragma unroll
        for (int rep = 0; rep < 2; rep++) {
            int i = t + rep * 256;
            int c = i >> 3, p = i & 7;
            float2 v = *(const float2*)&t8n[c * K7 + k0 + 2 * p];
            float h0 = bfround(v.x), h1 = bfround(v.y);
            A_hi[c * 9 + p] = bfpair(h0, h1);
            A_lo[c * 9 + p] = bfpair(v.x - h0, v.y - h1);
        }
        // ---- B build: 128 s x 16 k -> 1024 words (hi & lo), unfold gather ----
#pragma unroll
        for (int rep = 0; rep < 4; rep++) {
            int i = t + rep * 256;
            int sl = i >> 3, p = i & 7;
            int s = s0 + sl;
            int h = s / 96, w = s - h * 96;
            int k = k0 + 2 * p;
            int cp = k / 7, j = k - cp * 7;
            int cp1 = cp, j1 = j + 1;
            if (j == 6) { cp1 = cp + 1; j1 = 0; }
            int wq0 = w + 2 * j - 6;
            int wq1 = w + 2 * j1 - 6;
            float v0 = (wq0 >= 0 && wq0 < 96) ? xn[cp * HWW + h * 96 + wq0] : 0.f;
            float v1 = (wq1 >= 0 && wq1 < 96) ? xn[cp1 * HWW + h * 96 + wq1] : 0.f;
            float h0 = bfround(v0), h1 = bfround(v1);
            B_hi[sl * 9 + p] = bfpair(h0, h1);
            B_lo[sl * 9 + p] = bfpair(v0 - h0, v1 - h1);
        }
        __syncthreads();

        // ---- fragments + mma ----
        uint32_t ah[4], al[4];
        {
            int r0 = (warp_m * 16 + lr) * 9;
            int r1 = (warp_m * 16 + 8 + lr) * 9;
            ah[0] = A_hi[r0 + lp];     ah[1] = A_hi[r1 + lp];
            ah[2] = A_hi[r0 + 4 + lp]; ah[3] = A_hi[r1 + 4 + lp];
            al[0] = A_lo[r0 + lp];     al[1] = A_lo[r1 + lp];
            al[2] = A_lo[r0 + 4 + lp]; al[3] = A_lo[r1 + 4 + lp];
        }
#pragma unroll
        for (int nt = 0; nt < 8; nt++) {
            int nb = (warp_n * 64 + nt * 8 + lr) * 9;
            uint32_t bh0 = B_hi[nb + lp], bh1 = B_hi[nb + 4 + lp];
            uint32_t bl0 = B_lo[nb + lp], bl1 = B_lo[nb + 4 + lp];
            mma16816(d[nt], ah, bh0, bh1);
            mma16816(d[nt], ah, bl0, bl1);
            mma16816(d[nt], al, bh0, bh1);
        }
    }

    // ---- epilogue: add t9, store float2 (s, s+1) ----
    const int c_a = warp_m * 16 + lr;
    const int c_b = c_a + 8;
    const float ta = t9s[c_a], tb = t9s[c_b];
#pragma unroll
    for (int nt = 0; nt < 8; nt++) {
        int sb = s0 + warp_n * 64 + nt * 8 + lp * 2;
        float2 o0 = make_float2(d[nt][0] + ta, d[nt][1] + ta);
        float2 o1 = make_float2(d[nt][2] + tb, d[nt][3] + tb);
        *(float2*)&out[((size_t)(n * HC + c_a)) * HWW + sb] = o0;
        *(float2*)&out[((size_t)(n * HC + c_b)) * HWW + sb] = o1;
    }
}

// ---------------------------------------------------------------------------
extern "C" void kernel_launch(void* const* d_in, const int* in_sizes, int n_in,
                              void* d_out, int out_size) {
    const float* x  = (const float*)d_in[0];
    const float* w3 = (const float*)d_in[1];
    const float* w4 = (const float*)d_in[2];
    const float* p5 = (const float*)d_in[3];
    const float* p6 = (const float*)d_in[4];
    const float* p8 = (const float*)d_in[5];
    float* out = (float*)d_out;

    k_init<<<512, 256>>>();
    k_t2<<<dim3(T2_NCH, HN), 64>>>(x);
    k_t6<<<dim3(12, HN), 256>>>(x, w4, p6);
    k_t9<<<dim3(3, HC, HN), 256>>>(x, w3);
    k_t8<<<dim3(14, HN), 256>>>(p5, p8);
    k_out_mma<<<dim3(72, HN), 256>>>(x, out);
}